// round 7
// baseline (speedup 1.0000x reference)
#include <cuda_runtime.h>

#define WIRE_DIM 32
#define NUM_WIRES 64
#define ROW_ELEMS (NUM_WIRES * WIRE_DIM)   // 2048
#define ROW_PAD 36                          // wire stride in smem floats (conflict-free float4)
#define ROWS_PER_BLOCK 4
#define THREADS (32 * ROWS_PER_BLOCK)

__global__ __launch_bounds__(THREADS)
void isinone_loss_kernel(const float* __restrict__ outputs,
                         const int* __restrict__ tests,      // int32 pairs (person, location)
                         const float* __restrict__ W1,
                         const float* __restrict__ b1,
                         const float* __restrict__ W2,
                         const float* __restrict__ b2,
                         float* __restrict__ out,
                         int B)
{
    // W1 transposed: s_w1t[h*64 + d] = W1[d][h]   (h<10, d<64)
    __shared__ __align__(16) float s_w1t[10 * 64];
    __shared__ __align__(16) float s_wires[ROWS_PER_BLOCK][NUM_WIRES * ROW_PAD];
    __shared__ float s_w2[10];
    __shared__ float s_b1[10];
    __shared__ float s_b2;
    __shared__ float s_a[ROWS_PER_BLOCK][10];   // b1 + person_vec @ W1_top

    const int tid = threadIdx.x;

    // ---- load + transpose weights (once per block) ----
    for (int i = tid; i < 640; i += THREADS) {
        int d = i / 10, h = i % 10;
        s_w1t[h * 64 + d] = W1[i];
    }
    if (tid < 10) { s_b1[tid] = b1[tid]; s_w2[tid] = W2[tid]; }
    if (tid == 0) s_b2 = b2[0];
    __syncthreads();

    const int warp = tid >> 5;
    const int lane = tid & 31;
    const int row  = blockIdx.x * ROWS_PER_BLOCK + warp;
    if (row >= B) return;

    // ---- stage this row gmem -> smem (coalesced LDG.128, conflict-free STS.128) ----
    const float4* grow = (const float4*)(outputs + (size_t)row * ROW_ELEMS);
    float* srow = s_wires[warp];
#pragma unroll
    for (int i = 0; i < 16; i++) {
        int j = i * 32 + lane;            // float4 index 0..511 (coalesced)
        float4 v = grow[j];
        int wire = j >> 3;                // 8 float4 per wire
        int k4   = (j & 7) << 2;
        *(float4*)&srow[wire * ROW_PAD + k4] = v;
    }
    __syncwarp();

    const int p   = tests[2 * row + 0];
    const int loc = tests[2 * row + 1];

    // ---- person projection (shared across all 64 wires): lanes 0..9 ----
    if (lane < 10) {
        float acc = s_b1[lane];
        const float* pv  = &srow[p * ROW_PAD];            // broadcast reads
        const float* w1h = &s_w1t[lane * 64];
#pragma unroll
        for (int k = 0; k < WIRE_DIM; k++) acc = fmaf(pv[k], w1h[k], acc);
        s_a[warp][lane] = acc;
    }
    __syncwarp();

    // ---- main MLP: lane handles wires (lane) and (lane+32) ----
    float acc0[10], acc1[10];
#pragma unroll
    for (int h = 0; h < 10; h++) { float a = s_a[warp][h]; acc0[h] = a; acc1[h] = a; }

    const float4* rA = (const float4*)&srow[lane * ROW_PAD];
    const float4* rB = (const float4*)&srow[(lane + 32) * ROW_PAD];
#pragma unroll
    for (int g = 0; g < 8; g++) {
        float4 va = rA[g];
        float4 vb = rB[g];
#pragma unroll
        for (int h = 0; h < 10; h++) {
            float4 w = *(const float4*)&s_w1t[h * 64 + WIRE_DIM + g * 4]; // broadcast
            acc0[h] = fmaf(va.x, w.x, acc0[h]);
            acc0[h] = fmaf(va.y, w.y, acc0[h]);
            acc0[h] = fmaf(va.z, w.z, acc0[h]);
            acc0[h] = fmaf(va.w, w.w, acc0[h]);
            acc1[h] = fmaf(vb.x, w.x, acc1[h]);
            acc1[h] = fmaf(vb.y, w.y, acc1[h]);
            acc1[h] = fmaf(vb.z, w.z, acc1[h]);
            acc1[h] = fmaf(vb.w, w.w, acc1[h]);
        }
    }

    // ---- head: relu + W2 ----
    float l0 = s_b2, l1 = s_b2;
#pragma unroll
    for (int h = 0; h < 10; h++) {
        l0 = fmaf(fmaxf(acc0[h], 0.f), s_w2[h], l0);
        l1 = fmaf(fmaxf(acc1[h], 0.f), s_w2[h], l1);
    }

    // ---- warp log-softmax over 64 logits (2 per lane) ----
    float m = fmaxf(l0, l1);
#pragma unroll
    for (int o = 16; o; o >>= 1) m = fmaxf(m, __shfl_xor_sync(0xffffffffu, m, o));
    float s = __expf(l0 - m) + __expf(l1 - m);
#pragma unroll
    for (int o = 16; o; o >>= 1) s += __shfl_xor_sync(0xffffffffu, s, o);
    float lse = m + __logf(s);

    float lsel = __shfl_sync(0xffffffffu, (loc < 32) ? l0 : l1, loc & 31);
    if (lane == 0) out[row] = lse - lsel;   // loss = -(logit[loc] - lse)
}

extern "C" void kernel_launch(void* const* d_in, const int* in_sizes, int n_in,
                              void* d_out, int out_size)
{
    const float* outputs = (const float*)d_in[0];
    const int*   tests   = (const int*)d_in[1];
    const float* W1      = (const float*)d_in[2];
    const float* b1      = (const float*)d_in[3];
    const float* W2      = (const float*)d_in[4];
    const float* b2      = (const float*)d_in[5];
    float* out = (float*)d_out;

    const int B = in_sizes[0] / ROW_ELEMS;
    const int grid = (B + ROWS_PER_BLOCK - 1) / ROWS_PER_BLOCK;
    isinone_loss_kernel<<<grid, THREADS>>>(outputs, tests, W1, b1, W2, b2, out, B);
}